// round 10
// baseline (speedup 1.0000x reference)
#include <cuda_runtime.h>
#include <math.h>

#define TT 2048

__device__ float g_MT[256 * 1024];                    // folded init matrix, [d][j]
__device__ float g_abias[1024];                       // folded layer0 bias
__device__ float g_A0[(size_t)TT * 32 * 1024];        // layer0 input gates [t][b][j]
// per-producer h slices: [slot 3][grp 4][cc 32][layer 2][b 8][c 8]
__device__ float g_hbuf[3 * 4 * 32 * 128];
__device__ unsigned g_ctrs[4096];                     // (grp*32+cc)*32, 128B padded

__device__ __forceinline__ float sigf(float x) {
    return __fdividef(1.f, 1.f + __expf(-x));
}
__device__ __forceinline__ float tanha(float x) {
    float y; asm("tanh.approx.f32 %0, %1;" : "=f"(y) : "f"(x)); return y;
}
__device__ __forceinline__ void ffma2(unsigned long long& d,
                                      unsigned long long a, unsigned long long b) {
    asm("fma.rn.f32x2 %0, %1, %2, %0;" : "+l"(d) : "l"(a), "l"(b));
}
__device__ __forceinline__ unsigned ld_acq(const unsigned* p) {
    unsigned v;
    asm volatile("ld.acquire.gpu.u32 %0, [%1];" : "=r"(v) : "l"(p) : "memory");
    return v;
}
__device__ __forceinline__ void red_rel(unsigned* p) {
    asm volatile("red.release.gpu.global.add.u32 [%0], 1;" :: "l"(p) : "memory");
}

// ---- K0: zero counters (every launch, before k3) ---------------------------
__global__ void k0_zero() {
    g_ctrs[blockIdx.x * 256 + threadIdx.x] = 0;
}

// ---- K1a: MT[d][j] = sum_h Wih0[j,h] * Winit[h,d] --------------------------
__global__ void k1_mt(const float* __restrict__ Wih, const float* __restrict__ Winit) {
    int d = (blockIdx.x & 7) * 32 + (threadIdx.x & 31);
    int j = (blockIdx.x >> 3) * 8 + (threadIdx.x >> 5);
    const float* wr = Wih + (size_t)j * 256;
    float s = 0.f;
#pragma unroll 4
    for (int h = 0; h < 256; ++h)
        s = fmaf(wr[h], Winit[(size_t)h * 256 + d], s);
    g_MT[(size_t)d * 1024 + j] = s;
}

// ---- K1b: abias[j] = Wih0[j,:]·b_init + bih0[j] + bhh0[j] ------------------
__global__ void k1_bias(const float* __restrict__ Wih, const float* __restrict__ binit,
                        const float* __restrict__ bih, const float* __restrict__ bhh) {
    int j = blockIdx.x * 256 + threadIdx.x;
    const float* wr = Wih + (size_t)j * 256;
    float s = bih[j] + bhh[j];
#pragma unroll 4
    for (int h = 0; h < 256; ++h) s = fmaf(wr[h], binit[h], s);
    g_abias[j] = s;
}

// ---- K2: A0 = input @ MT + abias  (65536 x 1024 x 256 SGEMM) ---------------
__global__ __launch_bounds__(256) void k2_gemm(const float* __restrict__ A) {
    __shared__ float As[16][132];
    __shared__ float Bs[16][64];
    const int tid = threadIdx.x;
    const int rowBase = blockIdx.y * 128;
    const int colBase = blockIdx.x * 64;
    const int ty = tid >> 4, tx = tid & 15;

    float acc[8][4];
#pragma unroll
    for (int i = 0; i < 8; ++i)
#pragma unroll
        for (int c = 0; c < 4; ++c) acc[i][c] = 0.f;

    for (int kt = 0; kt < 256; kt += 16) {
#pragma unroll
        for (int rep = 0; rep < 2; ++rep) {
            int e = tid + rep * 256;
            int m = e >> 2, q = e & 3;
            float4 v = *(const float4*)(A + (size_t)(rowBase + m) * 256 + kt + q * 4);
            As[q * 4 + 0][m] = v.x; As[q * 4 + 1][m] = v.y;
            As[q * 4 + 2][m] = v.z; As[q * 4 + 3][m] = v.w;
        }
        {
            int kr = tid >> 4, q = tid & 15;
            *(float4*)&Bs[kr][q * 4] =
                *(const float4*)(g_MT + (size_t)(kt + kr) * 1024 + colBase + q * 4);
        }
        __syncthreads();
#pragma unroll
        for (int k = 0; k < 16; ++k) {
            float4 bv = *(float4*)&Bs[k][tx * 4];
            float4 a0 = *(float4*)&As[k][ty * 8];
            float4 a1 = *(float4*)&As[k][ty * 8 + 4];
#define FM(i, av) acc[i][0]=fmaf(av,bv.x,acc[i][0]); acc[i][1]=fmaf(av,bv.y,acc[i][1]); \
                  acc[i][2]=fmaf(av,bv.z,acc[i][2]); acc[i][3]=fmaf(av,bv.w,acc[i][3]);
            FM(0, a0.x) FM(1, a0.y) FM(2, a0.z) FM(3, a0.w)
            FM(4, a1.x) FM(5, a1.y) FM(6, a1.z) FM(7, a1.w)
#undef FM
        }
        __syncthreads();
    }
    float4 bias = *(const float4*)(g_abias + colBase + tx * 4);
#pragma unroll
    for (int i = 0; i < 8; ++i) {
        float4 r;
        r.x = acc[i][0] + bias.x; r.y = acc[i][1] + bias.y;
        r.z = acc[i][2] + bias.z; r.w = acc[i][3] + bias.w;
        *(float4*)(g_A0 + (size_t)(rowBase + ty * 8 + i) * 1024 + colBase + tx * 4) = r;
    }
}

// ---- K3: persistent recurrent kernel, per-cell self-publishing -------------
// 4 groups x 32 CTAs. Group g owns batches [8g,8g+8); CTA cc owns cols
// [8cc,8cc+8) of BOTH layers. Phase p computes h0[p] and h1[p-1].
// Publish: each tail thread stcg's its cell then red.release(+1) on the
// CTA counter. Consumers poll counter >= 128*p with acquire loads.
// SMEM floats: sw 0 (24960), sh0 24960 (2080), sh1 27040 (2080),
// sred 29120 (4608), sb1 33728 (32), sgate 33760 (524).
// Total 34284 fl = 137136 B.
__global__ __launch_bounds__(512, 1) void k3_rec(
    const float* __restrict__ Wih, const float* __restrict__ Whh,
    const float* __restrict__ bih, const float* __restrict__ bhh,
    const float* __restrict__ h0in, const float* __restrict__ c0in,
    float* __restrict__ out)
{
    extern __shared__ float sm[];
    float* sw  = sm;
    float* sh0 = sm + 24960;
    float* sh1 = sm + 27040;
    unsigned long long* sred = (unsigned long long*)(sm + 29120);
    float* sb1 = sm + 33728;
    float* sgate = sm + 33760;          // 4 arrays at +0,+132,+264,+396

    const int tid = threadIdx.x;
    const int bx = blockIdx.x;
    const int grp = bx >> 5;            // group 0..3
    const int cc  = bx & 31;            // cta in group
    const int col0 = cc * 8;            // global col base
    const int b0g  = grp * 8;           // global batch base

    const int kh   = tid >> 7;          // 0..3 k-quarter
    const int q    = tid & 127;
    const int rloc = q >> 2;            // 0..31 local row (cl*4+gt)
    const int bp   = q & 3;             // batch pair

    // persistent weights: m0=Whh0, m1=Wih1, m2=Whh1 (layer stride 262144)
    for (int e = tid; e < 6144; e += 512) {
        int m = e >> 11, rr = (e >> 6) & 31, kq = e & 63;
        int j = (rr & 3) * 256 + col0 + (rr >> 2);
        const float* base = (m == 0) ? (Whh + (size_t)j * 256)
                          : (m == 1) ? (Wih + 262144 + (size_t)j * 256)
                                     : (Whh + 262144 + (size_t)j * 256);
        *(float4*)&sw[(m * 32 + rr) * 260 + kq * 4] = *(const float4*)(base + kq * 4);
    }
    if (tid < 32) {
        int j = (tid & 3) * 256 + col0 + (tid >> 2);
        sb1[tid] = bih[1024 + j] + bhh[1024 + j];
    }
    __syncthreads();
    const float b1v = sb1[rloc];

    const float* wp0 = sw + rloc * 260 + kh * 64;
    const float* wp1 = wp0 + 8320;      // +32*260
    const float* wp2 = wp0 + 16640;     // +64*260
    const int bA = bp * 2, bB = bp * 2 + 1;   // local batches
    const float* h0a = sh0 + bA * 260 + kh * 64;
    const float* h0b = sh0 + bB * 260 + kh * 64;
    const float* h1a = sh1 + bA * 260 + kh * 64;
    const float* h1b = sh1 + bB * 260 + kh * 64;
    const int slot = (rloc * 4 + bp) * 6;
    const int jrow = (rloc & 3) * 256 + col0 + (rloc >> 2);
    const size_t a0iA = (size_t)(b0g + bA) * 1024 + jrow;
    const size_t a0iB = a0iA + 1024;

    // staging map: 16 threads per producer (layer x 8 local batches)
    const int pc  = tid >> 4;           // producer cta 0..31
    const int sub = tid & 15;
    const int lay = sub >> 3;           // 0 = h0, 1 = h1
    const int sb  = sub & 7;            // local batch
    float* sdst = (lay ? sh1 : sh0) + sb * 260 + pc * 8;
    const unsigned* ctrp = g_ctrs + (grp * 32 + pc) * 32;
    const float* initsrc = h0in + lay * 8192 + (size_t)(b0g + sb) * 256 + pc * 8;
    const float* slicebase = g_hbuf + grp * 4096 + pc * 128 + lay * 64 + sb * 8;

    // tail map: one cell per kh==0 thread; cell state lives in a register
    const int tlayer = q >> 6;          // 0 or 1
    const int tcell = q & 63;
    const int tcl = tcell >> 3, tb = tcell & 7;
    const int tbp = tb >> 1;
    const int tgbase = ((tb & 1) ? 132 : 0) + (tlayer ? 264 : 0);
    const int tcolg = col0 + tcl;
    const int tbg = b0g + tb;
    float* myslice = g_hbuf + grp * 4096 + cc * 128 + tlayer * 64 + tb * 8 + tcl;
    unsigned* myctr = g_ctrs + (grp * 32 + cc) * 32;
    float creg = 0.f;
    if (kh == 0) creg = c0in[tlayer * 8192 + (size_t)tbg * 256 + tcolg];

    for (int p = 0; p <= TT; ++p) {
        float a0vA = 0.f, a0vB = 0.f;
        if (kh == 0 && p < TT) {
            a0vA = __ldcs(g_A0 + (size_t)p * 32768 + a0iA);
            a0vB = __ldcs(g_A0 + (size_t)p * 32768 + a0iB);
        }
        // ---- dataflow staging: poll producer counter, fetch 32B slice ----
        const bool fromInit = lay ? (p <= 1) : (p == 0);
        if (fromInit) {
            float4 v0 = *(const float4*)(initsrc);
            float4 v1 = *(const float4*)(initsrc + 4);
            *(float4*)(sdst) = v0;
            *(float4*)(sdst + 4) = v1;
        } else {
            unsigned tgt = 128u * (unsigned)p;
            while (ld_acq(ctrp) < tgt) { }
            const float* sp = slicebase + ((p + 2) % 3) * 16384;
            float4 v0 = __ldcg((const float4*)sp);
            float4 v1 = __ldcg((const float4*)(sp + 4));
            *(float4*)(sdst) = v0;
            *(float4*)(sdst + 4) = v1;
        }
        __syncthreads();

        unsigned long long a0A = 0ull, a0B = 0ull, a1A = 0ull,
                           a1B = 0ull, a2A = 0ull, a2B = 0ull;
#pragma unroll
        for (int t = 0; t < 16; ++t) {
            ulonglong2 w0 = *(const ulonglong2*)(wp0 + t * 4);
            ulonglong2 w1 = *(const ulonglong2*)(wp1 + t * 4);
            ulonglong2 w2 = *(const ulonglong2*)(wp2 + t * 4);
            ulonglong2 hA = *(const ulonglong2*)(h0a + t * 4);
            ulonglong2 hB = *(const ulonglong2*)(h0b + t * 4);
            ulonglong2 gA = *(const ulonglong2*)(h1a + t * 4);
            ulonglong2 gB = *(const ulonglong2*)(h1b + t * 4);
            ffma2(a0A, w0.x, hA.x); ffma2(a0A, w0.y, hA.y);
            ffma2(a0B, w0.x, hB.x); ffma2(a0B, w0.y, hB.y);
            ffma2(a1A, w1.x, hA.x); ffma2(a1A, w1.y, hA.y);
            ffma2(a1B, w1.x, hB.x); ffma2(a1B, w1.y, hB.y);
            ffma2(a2A, w2.x, gA.x); ffma2(a2A, w2.y, gA.y);
            ffma2(a2B, w2.x, gB.x); ffma2(a2B, w2.y, gB.y);
        }
        if (kh != 0) {
            unsigned long long* d = sred + (size_t)(kh - 1) * 768;
            d[slot + 0] = a0A; d[slot + 1] = a1A; d[slot + 2] = a2A;
            d[slot + 3] = a0B; d[slot + 4] = a1B; d[slot + 5] = a2B;
        }
        __syncthreads();
        // kh!=0 warps fall through to next-phase staging (overlaps tail)

        if (kh == 0) {
            float2 p0A = *(float2*)&a0A, p1A = *(float2*)&a1A, p2A = *(float2*)&a2A;
            float2 p0B = *(float2*)&a0B, p1B = *(float2*)&a1B, p2B = *(float2*)&a2B;
#pragma unroll
            for (int kk = 0; kk < 3; ++kk) {
                const unsigned long long* d = sred + (size_t)kk * 768;
                float2 q0 = *(float2*)&d[slot + 0]; p0A.x += q0.x; p0A.y += q0.y;
                float2 q1 = *(float2*)&d[slot + 1]; p1A.x += q1.x; p1A.y += q1.y;
                float2 q2 = *(float2*)&d[slot + 2]; p2A.x += q2.x; p2A.y += q2.y;
                float2 q3 = *(float2*)&d[slot + 3]; p0B.x += q3.x; p0B.y += q3.y;
                float2 q4 = *(float2*)&d[slot + 4]; p1B.x += q4.x; p1B.y += q4.y;
                float2 q5 = *(float2*)&d[slot + 5]; p2B.x += q5.x; p2B.y += q5.y;
            }
            int gidx = rloc * 4 + bp;
            sgate[gidx + 0]   = a0vA + p0A.x + p0A.y;
            sgate[gidx + 132] = a0vB + p0B.x + p0B.y;
            sgate[gidx + 264] = p1A.x + p1A.y + p2A.x + p2A.y + b1v;
            sgate[gidx + 396] = p1B.x + p1B.y + p2B.x + p2B.y + b1v;
            asm volatile("bar.sync 1, 128;" ::: "memory");

            // ---- parallel tail: one cell per thread, self-publishing ----
            float gi = sgate[tgbase + (tcl * 4 + 0) * 4 + tbp];
            float gf = sgate[tgbase + (tcl * 4 + 1) * 4 + tbp];
            float gg = sgate[tgbase + (tcl * 4 + 2) * 4 + tbp];
            float go = sgate[tgbase + (tcl * 4 + 3) * 4 + tbp];
            if (tlayer == 0) {
                if (p < TT) {
                    float cn = fmaf(sigf(gf), creg, sigf(gi) * tanha(gg));
                    creg = cn;
                    __stcg(myslice + (p % 3) * 16384, sigf(go) * tanha(cn));
                }
            } else {
                if (p >= 1) {
                    float cn = fmaf(sigf(gf), creg, sigf(gi) * tanha(gg));
                    float hn = sigf(go) * tanha(cn);
                    creg = cn;
                    __stcg(myslice + (p % 3) * 16384, hn);
                    out[(size_t)(p - 1) * 16384 + tbg * 512 + tcolg] = hn;
                }
            }
            red_rel(myctr);     // orders this thread's stcg before the +1
        }
        // no block barrier here: next staging self-synchronizes via counters
    }
}

// ---- K4: backward half = h1[T-1] broadcast over t --------------------------
__global__ void k4_fill(float* __restrict__ out) {
    size_t i = (size_t)blockIdx.x * 256 + threadIdx.x;   // over 2048*32*64 f4
    int u4 = (int)(i & 63);
    size_t tb = i >> 6;
    int b = (int)(tb & 31);
    float4 v = *(const float4*)(out + (size_t)2047 * 16384 + b * 512 + u4 * 4);
    *(float4*)(out + tb * 512 + 256 + u4 * 4) = v;
}

extern "C" void kernel_launch(void* const* d_in, const int* in_sizes, int n_in,
                              void* d_out, int out_size) {
    const float* input = (const float*)d_in[0];
    const float* Winit = (const float*)d_in[1];
    const float* binit = (const float*)d_in[2];
    const float* Wih   = (const float*)d_in[3];
    const float* Whh   = (const float*)d_in[4];
    const float* bih   = (const float*)d_in[5];
    const float* bhh   = (const float*)d_in[6];
    const float* h0in  = (const float*)d_in[7];
    const float* c0in  = (const float*)d_in[8];
    float* out = (float*)d_out;

    cudaFuncSetAttribute(k3_rec, cudaFuncAttributeMaxDynamicSharedMemorySize, 137136);

    k0_zero<<<16, 256>>>();
    k1_mt<<<1024, 256>>>(Wih, Winit);
    k1_bias<<<4, 256>>>(Wih, binit, bih, bhh);
    k2_gemm<<<dim3(16, 512), 256>>>(input);
    k3_rec<<<128, 512, 137136>>>(Wih, Whh, bih, bhh, h0in, c0in, out);
    k4_fill<<<16384, 256>>>(out);
}